// round 4
// baseline (speedup 1.0000x reference)
#include <cuda_runtime.h>
#include <cstddef>

#define NB   16
#define NS   2048
#define DIN  256
#define DE   512
#define DK   512
#define DV   512
#define MROWS (NB*NS)   // 32768

// Scratch (static __device__ arrays: allocation-guard safe)
__device__ float g_e[(size_t)MROWS * DE];        // 64 MiB
__device__ float g_q[(size_t)MROWS * DK];        // 64 MiB
__device__ float g_k[(size_t)MROWS * DK];        // 64 MiB
__device__ float g_v[(size_t)MROWS * DV];        // 64 MiB
__device__ float g_s[(size_t)NB * NS * NS];      // 256 MiB

// ---------------------------------------------------------------------------
// Packed f32x2 helpers (Blackwell: doubles fp32 FMA throughput vs scalar FFMA)
// ---------------------------------------------------------------------------
__device__ __forceinline__ void fma2(unsigned long long& d,
                                     unsigned long long a,
                                     unsigned long long b) {
    asm("fma.rn.f32x2 %0, %1, %2, %0;" : "+l"(d) : "l"(a), "l"(b));
}
__device__ __forceinline__ unsigned long long splat2(float s) {
    unsigned long long d;
    unsigned u = __float_as_uint(s);
    asm("mov.b64 %0, {%1, %1};" : "=l"(d) : "r"(u));
    return d;
}

// ---------------------------------------------------------------------------
// Tiled fp32 GEMM, 128x128x16 block tile, 8x8 per thread, 256 threads.
// Software-pipelined: next K-tile's global loads issue right after the
// barrier, overlapping with the current tile's FMA phase.
//   BT = false : C[M,N] = A[M,K] * B[K,N]      (row-major)
//   BT = true  : C[M,N] = A[M,K] * B[N,K]^T    (both operands K-contiguous)
// Batched via blockIdx.z with element strides sA/sB/sC.
// All dims are multiples of 128 (M,N) and 16 (K) here: no bounds checks.
// ---------------------------------------------------------------------------
template <bool BT>
__global__ void __launch_bounds__(256)
sgemm_kernel(const float* __restrict__ A, const float* __restrict__ Bm,
             float* __restrict__ C, int M, int N, int K,
             size_t sA, size_t sB, size_t sC)
{
    A  += (size_t)blockIdx.z * sA;
    Bm += (size_t)blockIdx.z * sB;
    C  += (size_t)blockIdx.z * sC;

    __shared__ float As[16][128];
    __shared__ float Bs[16][128];

    const int tid = threadIdx.x;
    const int tx = tid & 15;        // 0..15 -> n
    const int ty = tid >> 4;        // 0..15 -> m
    const int m0 = blockIdx.y * 128;
    const int n0 = blockIdx.x * 128;

    // Per-thread gmem->smem staging coordinates (constant across K-steps)
    const int fa0 = tid,        fa1 = tid + 256;       // A float4 indices
    const int ar0 = fa0 >> 2,   ac0 = (fa0 & 3) << 2;  // A row / k-offset
    const int ar1 = fa1 >> 2,   ac1 = (fa1 & 3) << 2;
    // B coordinates depend on layout
    const int bKr0 = fa0 >> 5,  bKc0 = (fa0 & 31) << 2;  // BT=false: k row, n col
    const int bKr1 = fa1 >> 5,  bKc1 = (fa1 & 31) << 2;
    const int bTr0 = fa0 >> 2,  bTc0 = (fa0 & 3) << 2;   // BT=true: n row, k col
    const int bTr1 = fa1 >> 2,  bTc1 = (fa1 & 3) << 2;

    // 8x8 accumulators as 32 packed f32x2 (pairs along n)
    unsigned long long acc2[8][4];
    #pragma unroll
    for (int i = 0; i < 8; i++)
        #pragma unroll
        for (int j = 0; j < 4; j++) acc2[i][j] = 0ull;

    // ---- prologue: fetch first K-tile into registers
    float4 ra0 = *(const float4*)(A + (size_t)(m0 + ar0) * K + ac0);
    float4 ra1 = *(const float4*)(A + (size_t)(m0 + ar1) * K + ac1);
    float4 rb0, rb1;
    if (BT) {
        rb0 = *(const float4*)(Bm + (size_t)(n0 + bTr0) * K + bTc0);
        rb1 = *(const float4*)(Bm + (size_t)(n0 + bTr1) * K + bTc1);
    } else {
        rb0 = *(const float4*)(Bm + (size_t)bKr0 * N + n0 + bKc0);
        rb1 = *(const float4*)(Bm + (size_t)bKr1 * N + n0 + bKc1);
    }

    for (int k0 = 0; k0 < K; k0 += 16) {
        // ---- commit staged registers to shared (A transposed to [k][m])
        As[ac0 + 0][ar0] = ra0.x; As[ac0 + 1][ar0] = ra0.y;
        As[ac0 + 2][ar0] = ra0.z; As[ac0 + 3][ar0] = ra0.w;
        As[ac1 + 0][ar1] = ra1.x; As[ac1 + 1][ar1] = ra1.y;
        As[ac1 + 2][ar1] = ra1.z; As[ac1 + 3][ar1] = ra1.w;
        if (BT) {
            Bs[bTc0 + 0][bTr0] = rb0.x; Bs[bTc0 + 1][bTr0] = rb0.y;
            Bs[bTc0 + 2][bTr0] = rb0.z; Bs[bTc0 + 3][bTr0] = rb0.w;
            Bs[bTc1 + 0][bTr1] = rb1.x; Bs[bTc1 + 1][bTr1] = rb1.y;
            Bs[bTc1 + 2][bTr1] = rb1.z; Bs[bTc1 + 3][bTr1] = rb1.w;
        } else {
            *(float4*)&Bs[bKr0][bKc0] = rb0;
            *(float4*)&Bs[bKr1][bKc1] = rb1;
        }
        __syncthreads();

        // ---- prefetch next K-tile (overlaps with compute below)
        const int kn = k0 + 16;
        if (kn < K) {
            ra0 = *(const float4*)(A + (size_t)(m0 + ar0) * K + kn + ac0);
            ra1 = *(const float4*)(A + (size_t)(m0 + ar1) * K + kn + ac1);
            if (BT) {
                rb0 = *(const float4*)(Bm + (size_t)(n0 + bTr0) * K + kn + bTc0);
                rb1 = *(const float4*)(Bm + (size_t)(n0 + bTr1) * K + kn + bTc1);
            } else {
                rb0 = *(const float4*)(Bm + (size_t)(kn + bKr0) * N + n0 + bKc0);
                rb1 = *(const float4*)(Bm + (size_t)(kn + bKr1) * N + n0 + bKc1);
            }
        }

        // ---- 16-deep FMA phase on current smem tile
        #pragma unroll
        for (int kk = 0; kk < 16; kk++) {
            float4 a0 = *(const float4*)&As[kk][ty * 8];
            float4 a1 = *(const float4*)&As[kk][ty * 8 + 4];
            ulonglong2 b0 = *(const ulonglong2*)&Bs[kk][tx * 8];
            ulonglong2 b1 = *(const ulonglong2*)&Bs[kk][tx * 8 + 4];
            unsigned long long rbp0 = b0.x, rbp1 = b0.y, rbp2 = b1.x, rbp3 = b1.y;
            float raf[8] = {a0.x, a0.y, a0.z, a0.w, a1.x, a1.y, a1.z, a1.w};
            #pragma unroll
            for (int i = 0; i < 8; i++) {
                unsigned long long rap = splat2(raf[i]);
                fma2(acc2[i][0], rap, rbp0);
                fma2(acc2[i][1], rap, rbp1);
                fma2(acc2[i][2], rap, rbp2);
                fma2(acc2[i][3], rap, rbp3);
            }
        }
        __syncthreads();
    }

    // ---- epilogue: unpack and store 8x8 as two float4 per row
    #pragma unroll
    for (int i = 0; i < 8; i++) {
        float4 v0, v1;
        v0.x = __uint_as_float((unsigned)(acc2[i][0]));
        v0.y = __uint_as_float((unsigned)(acc2[i][0] >> 32));
        v0.z = __uint_as_float((unsigned)(acc2[i][1]));
        v0.w = __uint_as_float((unsigned)(acc2[i][1] >> 32));
        v1.x = __uint_as_float((unsigned)(acc2[i][2]));
        v1.y = __uint_as_float((unsigned)(acc2[i][2] >> 32));
        v1.z = __uint_as_float((unsigned)(acc2[i][3]));
        v1.w = __uint_as_float((unsigned)(acc2[i][3] >> 32));
        float* cp = C + (size_t)(m0 + ty * 8 + i) * N + n0 + tx * 8;
        *(float4*)cp       = v0;
        *(float4*)(cp + 4) = v1;
    }
}

// ---------------------------------------------------------------------------
// Row softmax over rows of length NS (2048). One block (256 thr) per row.
// Numerically stable (max subtraction); values kept in registers.
// ---------------------------------------------------------------------------
__global__ void __launch_bounds__(256)
softmax_rows_kernel(float* __restrict__ P)
{
    float* p = P + (size_t)blockIdx.x * NS;
    const int t = threadIdx.x;

    float4 a = *(const float4*)(p + 4 * t);
    float4 b = *(const float4*)(p + 1024 + 4 * t);

    float m = fmaxf(fmaxf(fmaxf(a.x, a.y), fmaxf(a.z, a.w)),
                    fmaxf(fmaxf(b.x, b.y), fmaxf(b.z, b.w)));

    __shared__ float red[8];
    #pragma unroll
    for (int o = 16; o; o >>= 1)
        m = fmaxf(m, __shfl_xor_sync(0xffffffffu, m, o));
    if ((t & 31) == 0) red[t >> 5] = m;
    __syncthreads();
    m = red[0];
    #pragma unroll
    for (int w = 1; w < 8; w++) m = fmaxf(m, red[w]);
    __syncthreads();

    a.x = expf(a.x - m); a.y = expf(a.y - m);
    a.z = expf(a.z - m); a.w = expf(a.w - m);
    b.x = expf(b.x - m); b.y = expf(b.y - m);
    b.z = expf(b.z - m); b.w = expf(b.w - m);

    float s = a.x + a.y + a.z + a.w + b.x + b.y + b.z + b.w;
    #pragma unroll
    for (int o = 16; o; o >>= 1)
        s += __shfl_xor_sync(0xffffffffu, s, o);
    if ((t & 31) == 0) red[t >> 5] = s;
    __syncthreads();
    s = red[0];
    #pragma unroll
    for (int w = 1; w < 8; w++) s += red[w];

    float inv = 1.0f / s;
    a.x *= inv; a.y *= inv; a.z *= inv; a.w *= inv;
    b.x *= inv; b.y *= inv; b.z *= inv; b.w *= inv;

    *(float4*)(p + 4 * t)        = a;
    *(float4*)(p + 1024 + 4 * t) = b;
}

// ---------------------------------------------------------------------------
// Launch: e = x@We ; q,k,v = e@W* ; S = qk^T (batched) ; softmax ; y = S@v
// ---------------------------------------------------------------------------
extern "C" void kernel_launch(void* const* d_in, const int* in_sizes, int n_in,
                              void* d_out, int out_size)
{
    const float* x  = (const float*)d_in[0];
    const float* We = (const float*)d_in[1];
    const float* Wk = (const float*)d_in[2];
    const float* Wq = (const float*)d_in[3];
    const float* Wv = (const float*)d_in[4];
    float* y = (float*)d_out;

    float *e, *q, *k, *v, *s;
    cudaGetSymbolAddress((void**)&e, g_e);
    cudaGetSymbolAddress((void**)&q, g_q);
    cudaGetSymbolAddress((void**)&k, g_k);
    cudaGetSymbolAddress((void**)&v, g_v);
    cudaGetSymbolAddress((void**)&s, g_s);

    // 1) e = x @ W_embed           [32768,256]x[256,512]
    sgemm_kernel<false><<<dim3(DE / 128, MROWS / 128, 1), 256>>>(
        x, We, e, MROWS, DE, DIN, 0, 0, 0);

    // 2) q,k,v = e @ W_{q,k,v}     [32768,512]x[512,512]
    sgemm_kernel<false><<<dim3(DK / 128, MROWS / 128, 1), 256>>>(
        e, Wq, q, MROWS, DK, DE, 0, 0, 0);
    sgemm_kernel<false><<<dim3(DK / 128, MROWS / 128, 1), 256>>>(
        e, Wk, k, MROWS, DK, DE, 0, 0, 0);
    sgemm_kernel<false><<<dim3(DV / 128, MROWS / 128, 1), 256>>>(
        e, Wv, v, MROWS, DV, DE, 0, 0, 0);

    // 3) scores S_b = q_b @ k_b^T  [2048,512]x[2048,512]^T, batched over b
    sgemm_kernel<true><<<dim3(NS / 128, NS / 128, NB), 256>>>(
        q, k, s, NS, NS, DK,
        (size_t)NS * DK, (size_t)NS * DK, (size_t)NS * NS);

    // 4) row softmax over keys
    softmax_rows_kernel<<<NB * NS, 256>>>(s);

    // 5) y_b = P_b @ v_b           [2048,2048]x[2048,512], batched over b
    sgemm_kernel<false><<<dim3(DV / 128, NS / 128, NB), 256>>>(
        s, v, y, NS, DV, NS,
        (size_t)NS * NS, (size_t)NS * DV, (size_t)NS * DV);
}

// round 6
// speedup vs baseline: 1.3908x; 1.3908x over previous
#include <cuda_runtime.h>
#include <cstdint>
#include <cstddef>

#define NB   16
#define NS   2048
#define DIN  256
#define DE   512
#define MROWS (NB*NS)   // 32768

// Scratch (static __device__ arrays: allocation-guard safe)
__device__ float g_e[(size_t)MROWS * DE];        // 64 MiB
__device__ float g_q[(size_t)MROWS * DE];        // 64 MiB
__device__ float g_k[(size_t)MROWS * DE];        // 64 MiB
__device__ float g_v[(size_t)MROWS * DE];        // 64 MiB
__device__ float g_s[(size_t)NB * NS * NS];      // 256 MiB

// ---------------------------------------------------------------------------
// Helpers
// ---------------------------------------------------------------------------
__device__ __forceinline__ uint32_t smem_u32(const void* p) {
    uint32_t a;
    asm("{ .reg .u64 t; cvta.to.shared.u64 t, %1; cvt.u32.u64 %0, t; }"
        : "=r"(a) : "l"(p));
    return a;
}
__device__ __forceinline__ float to_tf32(float x) {
    float r;
    asm("cvt.rna.tf32.f32 %0, %1;" : "=f"(r) : "f"(x));
    return r;
}
// m16n8k8 tf32 MMA (sm_80+ base feature; legal on target sm_103)
__device__ __forceinline__ void mma8(float* c, const uint32_t* a, const uint32_t* b) {
    asm volatile(
        "mma.sync.aligned.m16n8k8.row.col.f32.tf32.tf32.f32 "
        "{%0,%1,%2,%3}, {%4,%5,%6,%7}, {%8,%9}, {%0,%1,%2,%3};"
        : "+f"(c[0]), "+f"(c[1]), "+f"(c[2]), "+f"(c[3])
        : "r"(a[0]), "r"(a[1]), "r"(a[2]), "r"(a[3]), "r"(b[0]), "r"(b[1]));
}
// Swizzled smem load: tile rows are 32 floats (128 B); XOR bits[4:6] with row&7.
__device__ __forceinline__ uint32_t lds_u(uint32_t base, int row, int kc) {
    uint32_t a = (uint32_t)(row * 128 + kc * 4);
    a ^= (a >> 3) & 0x70;
    uint32_t v;
    asm volatile("ld.shared.b32 %0, [%1];" : "=r"(v) : "r"(base + a));
    return v;
}

// ---------------------------------------------------------------------------
// SMEM layout: 2 stages x (A_hi, A_lo, B_hi, B_lo), each 128 rows x 32 fp32.
// ---------------------------------------------------------------------------
static constexpr int TILE_B     = 16384;
static constexpr int STAGE_B    = 4 * TILE_B;   // 64 KB
static constexpr int SMEM_TOTAL = 2 * STAGE_B;  // 128 KB
#define A_HI(s) ((s) * STAGE_B)
#define A_LO(s) (A_HI(s) + TILE_B)
#define B_HI(s) (A_HI(s) + 2 * TILE_B)
#define B_LO(s) (A_HI(s) + 3 * TILE_B)

// Split + swizzled store of one float4 (16 B) at byte offset `off` in a tile.
__device__ __forceinline__ void split_store(char* sm, int ohi, int olo,
                                            uint32_t off, float4 x) {
    float4 h, l;
    h.x = to_tf32(x.x); l.x = x.x - h.x;
    h.y = to_tf32(x.y); l.y = x.y - h.y;
    h.z = to_tf32(x.z); l.z = x.z - h.z;
    h.w = to_tf32(x.w); l.w = x.w - h.w;
    uint32_t sw = off ^ ((off >> 3) & 0x70);
    *(float4*)(sm + ohi + sw) = h;
    *(float4*)(sm + olo + sw) = l;
}

// ---------------------------------------------------------------------------
// tf32x3 GEMM on mma.sync. 128x128 C tile per CTA, K in chunks of 32,
// double-buffered smem, gmem prefetch overlapped with compute.
//   BT = false : C[M,N] = A[M,K] * B[K,N]
//   BT = true  : C[M,N] = A[M,K] * B[N,K]^T
// 256 threads = 8 warps, each warp computes 64(m) x 32(n).
// ---------------------------------------------------------------------------
template <bool BT>
__global__ void __launch_bounds__(256, 1)
mma_gemm(const float* __restrict__ A, const float* __restrict__ Bm,
         float* __restrict__ C, int M, int N, int K,
         size_t sA, size_t sB, size_t sC)
{
    extern __shared__ char sm[];
    const uint32_t sb = smem_u32(sm);
    const int tid = threadIdx.x;
    const int w = tid >> 5, l = tid & 31;
    const int g = l >> 2, tg = l & 3;      // fragment lane coords
    const int wm = w >> 2, wn = w & 3;     // warp grid 2(m) x 4(n)

    A  += (size_t)blockIdx.z * sA;
    Bm += (size_t)blockIdx.z * sB;
    C  += (size_t)blockIdx.z * sC;
    const int m0 = blockIdx.y * 128;
    const int n0 = blockIdx.x * 128;

    // Staging coords: 256 threads cover 128 rows x 2 halves of 16 floats.
    const int ar = tid >> 1, ah_ = tid & 1;
    const float* pA = A + (size_t)(m0 + ar) * K + ah_ * 16;
    const float* pBk = BT ? (Bm + (size_t)(n0 + ar) * K + ah_ * 16) : nullptr;
    const int bn = tid & 127, bkh = tid >> 7;   // trans path: col n, k-half

    float acc[4][4][4];
    #pragma unroll
    for (int i = 0; i < 4; i++)
        #pragma unroll
        for (int j = 0; j < 4; j++)
            #pragma unroll
            for (int r = 0; r < 4; r++) acc[i][j][r] = 0.f;

    float4 fa[4], fb[4];
    float  fbt[16];

    const int nch = K / 32;

    // ---- fetch chunk 0
    #pragma unroll
    for (int j = 0; j < 4; j++) fa[j] = *(const float4*)(pA + j * 4);
    if (BT) {
        #pragma unroll
        for (int j = 0; j < 4; j++) fb[j] = *(const float4*)(pBk + j * 4);
    } else {
        const float* pB = Bm + (size_t)(bkh * 16) * N + n0 + bn;
        #pragma unroll
        for (int t = 0; t < 16; t++) fbt[t] = pB[(size_t)t * N];
    }
    // ---- commit chunk 0 -> stage 0
    {
        const uint32_t ab = (uint32_t)(ar * 128 + ah_ * 64);
        #pragma unroll
        for (int j = 0; j < 4; j++) split_store(sm, A_HI(0), A_LO(0), ab + j * 16, fa[j]);
        if (BT) {
            #pragma unroll
            for (int j = 0; j < 4; j++) split_store(sm, B_HI(0), B_LO(0), ab + j * 16, fb[j]);
        } else {
            const uint32_t bb = (uint32_t)(bn * 128 + bkh * 64);
            #pragma unroll
            for (int gi = 0; gi < 4; gi++) {
                float4 x = make_float4(fbt[gi*4+0], fbt[gi*4+1], fbt[gi*4+2], fbt[gi*4+3]);
                split_store(sm, B_HI(0), B_LO(0), bb + gi * 16, x);
            }
        }
    }
    __syncthreads();

    for (int c = 0; c < nch; c++) {
        const int s = c & 1;

        // ---- fetch chunk c+1 (overlaps with compute below)
        if (c + 1 < nch) {
            const int k0 = (c + 1) * 32;
            #pragma unroll
            for (int j = 0; j < 4; j++) fa[j] = *(const float4*)(pA + k0 + j * 4);
            if (BT) {
                #pragma unroll
                for (int j = 0; j < 4; j++) fb[j] = *(const float4*)(pBk + k0 + j * 4);
            } else {
                const float* pB = Bm + (size_t)(k0 + bkh * 16) * N + n0 + bn;
                #pragma unroll
                for (int t = 0; t < 16; t++) fbt[t] = pB[(size_t)t * N];
            }
        }

        // ---- compute on stage s: 4 k-steps of 8
        const uint32_t bAh = sb + A_HI(s), bAl = sb + A_LO(s);
        const uint32_t bBh = sb + B_HI(s), bBl = sb + B_LO(s);
        #pragma unroll
        for (int ks = 0; ks < 4; ks++) {
            const int kb = ks * 8;
            uint32_t ahf[4][4], alf[4][4], bhf[4][2], blf[4][2];
            #pragma unroll
            for (int mt = 0; mt < 4; mt++) {
                const int r0 = wm * 64 + mt * 16 + g;
                ahf[mt][0] = lds_u(bAh, r0,     kb + tg);
                ahf[mt][1] = lds_u(bAh, r0 + 8, kb + tg);
                ahf[mt][2] = lds_u(bAh, r0,     kb + tg + 4);
                ahf[mt][3] = lds_u(bAh, r0 + 8, kb + tg + 4);
                alf[mt][0] = lds_u(bAl, r0,     kb + tg);
                alf[mt][1] = lds_u(bAl, r0 + 8, kb + tg);
                alf[mt][2] = lds_u(bAl, r0,     kb + tg + 4);
                alf[mt][3] = lds_u(bAl, r0 + 8, kb + tg + 4);
            }
            #pragma unroll
            for (int nt = 0; nt < 4; nt++) {
                const int rn = wn * 32 + nt * 8 + g;
                bhf[nt][0] = lds_u(bBh, rn, kb + tg);
                bhf[nt][1] = lds_u(bBh, rn, kb + tg + 4);
                blf[nt][0] = lds_u(bBl, rn, kb + tg);
                blf[nt][1] = lds_u(bBl, rn, kb + tg + 4);
            }
            #pragma unroll
            for (int mt = 0; mt < 4; mt++)
                #pragma unroll
                for (int nt = 0; nt < 4; nt++) {
                    mma8(acc[mt][nt], ahf[mt], bhf[nt]);
                    mma8(acc[mt][nt], alf[mt], bhf[nt]);
                    mma8(acc[mt][nt], ahf[mt], blf[nt]);
                }
        }

        // ---- commit chunk c+1 -> stage 1-s
        if (c + 1 < nch) {
            const int sn = (c + 1) & 1;
            const uint32_t ab = (uint32_t)(ar * 128 + ah_ * 64);
            #pragma unroll
            for (int j = 0; j < 4; j++) split_store(sm, A_HI(sn), A_LO(sn), ab + j * 16, fa[j]);
            if (BT) {
                #pragma unroll
                for (int j = 0; j < 4; j++) split_store(sm, B_HI(sn), B_LO(sn), ab + j * 16, fb[j]);
            } else {
                const uint32_t bb = (uint32_t)(bn * 128 + bkh * 64);
                #pragma unroll
                for (int gi = 0; gi < 4; gi++) {
                    float4 x = make_float4(fbt[gi*4+0], fbt[gi*4+1], fbt[gi*4+2], fbt[gi*4+3]);
                    split_store(sm, B_HI(sn), B_LO(sn), bb + gi * 16, x);
                }
            }
        }
        __syncthreads();
    }

    // ---- epilogue: write 64x32 warp tile
    #pragma unroll
    for (int mt = 0; mt < 4; mt++)
        #pragma unroll
        for (int nt = 0; nt < 4; nt++) {
            const int row = m0 + wm * 64 + mt * 16 + g;
            const int col = n0 + wn * 32 + nt * 8 + 2 * tg;
            float2 v0 = make_float2(acc[mt][nt][0], acc[mt][nt][1]);
            float2 v1 = make_float2(acc[mt][nt][2], acc[mt][nt][3]);
            *(float2*)(C + (size_t)row * N + col)       = v0;
            *(float2*)(C + (size_t)(row + 8) * N + col) = v1;
        }
}

// ---------------------------------------------------------------------------
// Row softmax over rows of length NS (2048). One block (256 thr) per row.
// ---------------------------------------------------------------------------
__global__ void __launch_bounds__(256)
softmax_rows_kernel(float* __restrict__ P)
{
    float* p = P + (size_t)blockIdx.x * NS;
    const int t = threadIdx.x;

    float4 a = *(const float4*)(p + 4 * t);
    float4 b = *(const float4*)(p + 1024 + 4 * t);

    float m = fmaxf(fmaxf(fmaxf(a.x, a.y), fmaxf(a.z, a.w)),
                    fmaxf(fmaxf(b.x, b.y), fmaxf(b.z, b.w)));

    __shared__ float red[8];
    #pragma unroll
    for (int o = 16; o; o >>= 1)
        m = fmaxf(m, __shfl_xor_sync(0xffffffffu, m, o));
    if ((t & 31) == 0) red[t >> 5] = m;
    __syncthreads();
    m = red[0];
    #pragma unroll
    for (int w = 1; w < 8; w++) m = fmaxf(m, red[w]);
    __syncthreads();

    a.x = expf(a.x - m); a.y = expf(a.y - m);
    a.z = expf(a.z - m); a.w = expf(a.w - m);
    b.x = expf(b.x - m); b.y = expf(b.y - m);
    b.z = expf(b.z - m); b.w = expf(b.w - m);

    float s = a.x + a.y + a.z + a.w + b.x + b.y + b.z + b.w;
    #pragma unroll
    for (int o = 16; o; o >>= 1)
        s += __shfl_xor_sync(0xffffffffu, s, o);
    if ((t & 31) == 0) red[t >> 5] = s;
    __syncthreads();
    s = red[0];
    #pragma unroll
    for (int w = 1; w < 8; w++) s += red[w];

    float inv = 1.0f / s;
    a.x *= inv; a.y *= inv; a.z *= inv; a.w *= inv;
    b.x *= inv; b.y *= inv; b.z *= inv; b.w *= inv;

    *(float4*)(p + 4 * t)        = a;
    *(float4*)(p + 1024 + 4 * t) = b;
}

// ---------------------------------------------------------------------------
// Launch: e = x@We ; q,k,v = e@W* ; S = qk^T (batched) ; softmax ; y = S@v
// ---------------------------------------------------------------------------
extern "C" void kernel_launch(void* const* d_in, const int* in_sizes, int n_in,
                              void* d_out, int out_size)
{
    const float* x  = (const float*)d_in[0];
    const float* We = (const float*)d_in[1];
    const float* Wk = (const float*)d_in[2];
    const float* Wq = (const float*)d_in[3];
    const float* Wv = (const float*)d_in[4];
    float* y = (float*)d_out;

    float *e, *q, *k, *v, *s;
    cudaGetSymbolAddress((void**)&e, g_e);
    cudaGetSymbolAddress((void**)&q, g_q);
    cudaGetSymbolAddress((void**)&k, g_k);
    cudaGetSymbolAddress((void**)&v, g_v);
    cudaGetSymbolAddress((void**)&s, g_s);

    cudaFuncSetAttribute(mma_gemm<false>,
                         cudaFuncAttributeMaxDynamicSharedMemorySize, SMEM_TOTAL);
    cudaFuncSetAttribute(mma_gemm<true>,
                         cudaFuncAttributeMaxDynamicSharedMemorySize, SMEM_TOTAL);

    // 1) e = x @ W_embed           [32768,256]x[256,512]
    mma_gemm<false><<<dim3(DE / 128, MROWS / 128, 1), 256, SMEM_TOTAL>>>(
        x, We, e, MROWS, DE, DIN, 0, 0, 0);

    // 2) q,k,v = e @ W_{q,k,v}     [32768,512]x[512,512]
    mma_gemm<false><<<dim3(DE / 128, MROWS / 128, 1), 256, SMEM_TOTAL>>>(
        e, Wq, q, MROWS, DE, DE, 0, 0, 0);
    mma_gemm<false><<<dim3(DE / 128, MROWS / 128, 1), 256, SMEM_TOTAL>>>(
        e, Wk, k, MROWS, DE, DE, 0, 0, 0);
    mma_gemm<false><<<dim3(DE / 128, MROWS / 128, 1), 256, SMEM_TOTAL>>>(
        e, Wv, v, MROWS, DE, DE, 0, 0, 0);

    // 3) scores S_b = q_b @ k_b^T  [2048,512]x[2048,512]^T, batched over b
    mma_gemm<true><<<dim3(NS / 128, NS / 128, NB), 256, SMEM_TOTAL>>>(
        q, k, s, NS, NS, DE,
        (size_t)NS * DE, (size_t)NS * DE, (size_t)NS * NS);

    // 4) row softmax over keys
    softmax_rows_kernel<<<NB * NS, 256>>>(s);

    // 5) y_b = P_b @ v_b           [2048,2048]x[2048,512], batched over b
    mma_gemm<false><<<dim3(DE / 128, NS / 128, NB), 256, SMEM_TOTAL>>>(
        s, v, y, NS, DE, NS,
        (size_t)NS * NS, (size_t)NS * DE, (size_t)NS * DE);
}

// round 7
// speedup vs baseline: 2.4534x; 1.7641x over previous
#include <cuda_runtime.h>
#include <cuda_fp16.h>
#include <cstdint>
#include <cstddef>

#define NB   16
#define NS   2048
#define DIN  256
#define DE   512
#define MROWS (NB*NS)   // 32768

// Scratch (static __device__ arrays: allocation-guard safe)
__device__ float g_e[(size_t)MROWS * DE];        // 64 MiB
__device__ float g_q[(size_t)MROWS * DE];        // 64 MiB
__device__ float g_k[(size_t)MROWS * DE];        // 64 MiB
__device__ float g_v[(size_t)MROWS * DE];        // 64 MiB
__device__ float g_s[(size_t)NB * NS * NS];      // 256 MiB

// ---------------------------------------------------------------------------
// Helpers
// ---------------------------------------------------------------------------
__device__ __forceinline__ uint32_t smem_u32(const void* p) {
    uint32_t a;
    asm("{ .reg .u64 t; cvta.to.shared.u64 t, %1; cvt.u32.u64 %0, t; }"
        : "=r"(a) : "l"(p));
    return a;
}
// SW128-style swizzle: XOR 16B-chunk bits [4:6] with row bits [7:9]
__device__ __forceinline__ uint32_t swz(uint32_t a) {
    return a ^ ((a >> 3) & 0x70);
}
// m16n8k16 fp16 MMA, fp32 accumulate (sm_80+ base feature)
__device__ __forceinline__ void mma16(float* c, const uint32_t* a, const uint32_t* b) {
    asm volatile(
        "mma.sync.aligned.m16n8k16.row.col.f32.f16.f16.f32 "
        "{%0,%1,%2,%3}, {%4,%5,%6,%7}, {%8,%9}, {%0,%1,%2,%3};"
        : "+f"(c[0]), "+f"(c[1]), "+f"(c[2]), "+f"(c[3])
        : "r"(a[0]), "r"(a[1]), "r"(a[2]), "r"(a[3]), "r"(b[0]), "r"(b[1]));
}
// ldmatrix x4 (b16, sm_75+ base feature)
__device__ __forceinline__ void ldsm4(uint32_t* r, uint32_t addr) {
    asm volatile(
        "ldmatrix.sync.aligned.m8n8.x4.shared.b16 {%0,%1,%2,%3}, [%4];"
        : "=r"(r[0]), "=r"(r[1]), "=r"(r[2]), "=r"(r[3]) : "r"(addr));
}
// Split 8 fp32 into hi/lo fp16 quads (lo = rn(x - hi), captures ~2^-22 rel)
__device__ __forceinline__ void split8(const float* f, uint4& hi, uint4& lo) {
    uint32_t h[4], l[4];
    #pragma unroll
    for (int i = 0; i < 4; i++) {
        __half h0 = __float2half_rn(f[2*i]), h1 = __float2half_rn(f[2*i+1]);
        float  r0 = f[2*i]   - __half2float(h0);
        float  r1 = f[2*i+1] - __half2float(h1);
        __half2 hh = __halves2half2(h0, h1);
        __half2 ll = __floats2half2_rn(r0, r1);
        h[i] = *reinterpret_cast<uint32_t*>(&hh);
        l[i] = *reinterpret_cast<uint32_t*>(&ll);
    }
    hi = make_uint4(h[0], h[1], h[2], h[3]);
    lo = make_uint4(l[0], l[1], l[2], l[3]);
}

// ---------------------------------------------------------------------------
// SMEM: per stage, A tile + B tile; each tile = 128 rows x 128 B where a row
// packs [k0..31 hi fp16 | k0..31 lo fp16]. 2 stages, 64 KB total.
// ---------------------------------------------------------------------------
static constexpr int TILE_B     = 128 * 128;      // 16 KB
static constexpr int STAGE_B    = 2 * TILE_B;     // 32 KB
static constexpr int SMEM_TOTAL = 2 * STAGE_B;    // 64 KB
#define A_OFF(s) ((s) * STAGE_B)
#define B_OFF(s) ((s) * STAGE_B + TILE_B)

// ---------------------------------------------------------------------------
// fp16x3 split GEMM on mma.sync + ldmatrix. 128x128 C tile per CTA,
// K-chunks of 32, double-buffered smem, 512 threads = 16 warps (32x32 each).
//   BT = false : C[M,N] = A[M,K] * B[K,N]
//   BT = true  : C[M,N] = A[M,K] * B[N,K]^T
// ---------------------------------------------------------------------------
template <bool BT>
__global__ void __launch_bounds__(512, 1)
mma_gemm(const float* __restrict__ A, const float* __restrict__ Bm,
         float* __restrict__ C, int M, int N, int K,
         size_t sA, size_t sB, size_t sC)
{
    extern __shared__ char sm[];
    const uint32_t sb = smem_u32(sm);
    const int tid = threadIdx.x;
    const int w = tid >> 5, l = tid & 31;
    const int g = l >> 2, tg = l & 3;      // mma lane coords
    const int lm = l >> 3, lr = l & 7;     // ldmatrix: matrix id, row-in-matrix
    const int wm = w >> 2, wn = w & 3;     // warp grid 4(m) x 4(n), 32x32 tiles

    A  += (size_t)blockIdx.z * sA;
    Bm += (size_t)blockIdx.z * sB;
    C  += (size_t)blockIdx.z * sC;
    const int m0 = blockIdx.y * 128;
    const int n0 = blockIdx.x * 128;

    // Staging coords: 512 threads cover a 128x32 fp32 tile, 8 floats each.
    const int ar = tid >> 2, aq = tid & 3;                  // row, k-quarter
    const float* pA  = A + (size_t)(m0 + ar) * K + aq * 8;
    const float* pBk = BT ? (Bm + (size_t)(n0 + ar) * K + aq * 8) : nullptr;
    const int bn = tid & 127, bkh = tid >> 7;               // trans: col, k-eighth

    float acc[2][4][4];
    #pragma unroll
    for (int i = 0; i < 2; i++)
        #pragma unroll
        for (int j = 0; j < 4; j++)
            #pragma unroll
            for (int r = 0; r < 4; r++) acc[i][j][r] = 0.f;

    float fa[8], fb[8];
    const int nch = K / 32;

    // ---- fetch chunk 0
    {
        float4 x = *(const float4*)(pA);
        float4 y = *(const float4*)(pA + 4);
        fa[0]=x.x; fa[1]=x.y; fa[2]=x.z; fa[3]=x.w;
        fa[4]=y.x; fa[5]=y.y; fa[6]=y.z; fa[7]=y.w;
        if (BT) {
            float4 u = *(const float4*)(pBk);
            float4 v = *(const float4*)(pBk + 4);
            fb[0]=u.x; fb[1]=u.y; fb[2]=u.z; fb[3]=u.w;
            fb[4]=v.x; fb[5]=v.y; fb[6]=v.z; fb[7]=v.w;
        } else {
            const float* pB = Bm + (size_t)(bkh * 8) * N + n0 + bn;
            #pragma unroll
            for (int t = 0; t < 8; t++) fb[t] = pB[(size_t)t * N];
        }
    }

    for (int c = 0; c < nch; c++) {
        const int s = c & 1;

        // ---- commit staged chunk -> stage s (hi | lo packed per row)
        {
            uint4 hi, lo;
            split8(fa, hi, lo);
            uint32_t off = (uint32_t)(ar * 128 + aq * 16);
            *(uint4*)(sm + A_OFF(s) + swz(off))      = hi;
            *(uint4*)(sm + A_OFF(s) + swz(off + 64)) = lo;
            split8(fb, hi, lo);
            if (BT) {
                *(uint4*)(sm + B_OFF(s) + swz(off))      = hi;
                *(uint4*)(sm + B_OFF(s) + swz(off + 64)) = lo;
            } else {
                uint32_t bo = (uint32_t)(bn * 128 + bkh * 16);
                *(uint4*)(sm + B_OFF(s) + swz(bo))      = hi;
                *(uint4*)(sm + B_OFF(s) + swz(bo + 64)) = lo;
            }
        }
        __syncthreads();

        // ---- fetch chunk c+1 (overlaps with compute below)
        if (c + 1 < nch) {
            const int k0 = (c + 1) * 32;
            float4 x = *(const float4*)(pA + k0);
            float4 y = *(const float4*)(pA + k0 + 4);
            fa[0]=x.x; fa[1]=x.y; fa[2]=x.z; fa[3]=x.w;
            fa[4]=y.x; fa[5]=y.y; fa[6]=y.z; fa[7]=y.w;
            if (BT) {
                float4 u = *(const float4*)(pBk + k0);
                float4 v = *(const float4*)(pBk + k0 + 4);
                fb[0]=u.x; fb[1]=u.y; fb[2]=u.z; fb[3]=u.w;
                fb[4]=v.x; fb[5]=v.y; fb[6]=v.z; fb[7]=v.w;
            } else {
                const float* pB = Bm + (size_t)(k0 + bkh * 8) * N + n0 + bn;
                #pragma unroll
                for (int t = 0; t < 8; t++) fb[t] = pB[(size_t)t * N];
            }
        }

        // ---- compute stage s: 2 k-steps of 16
        const uint32_t bA = sb + A_OFF(s), bB = sb + B_OFF(s);
        #pragma unroll
        for (int ks = 0; ks < 2; ks++) {
            uint32_t ah[2][4], al[2][4], bh[2][4], bl[2][4];
            #pragma unroll
            for (int mt = 0; mt < 2; mt++) {
                uint32_t off = (uint32_t)((wm * 32 + mt * 16 + (lm & 1) * 8 + lr) * 128
                                          + ks * 32 + (lm >> 1) * 16);
                ldsm4(ah[mt], bA + swz(off));
                ldsm4(al[mt], bA + swz(off + 64));
            }
            #pragma unroll
            for (int np = 0; np < 2; np++) {
                uint32_t off = (uint32_t)((wn * 32 + np * 16 + (lm >> 1) * 8 + lr) * 128
                                          + ks * 32 + (lm & 1) * 16);
                ldsm4(bh[np], bB + swz(off));
                ldsm4(bl[np], bB + swz(off + 64));
            }
            #pragma unroll
            for (int mt = 0; mt < 2; mt++)
                #pragma unroll
                for (int nt = 0; nt < 4; nt++) {
                    const uint32_t* bhf = &bh[nt >> 1][(nt & 1) * 2];
                    const uint32_t* blf = &bl[nt >> 1][(nt & 1) * 2];
                    mma16(acc[mt][nt], ah[mt], bhf);   // hi*hi
                    mma16(acc[mt][nt], al[mt], bhf);   // lo*hi
                    mma16(acc[mt][nt], ah[mt], blf);   // hi*lo
                }
        }
    }

    // ---- epilogue: write 32x32 warp tile
    #pragma unroll
    for (int mt = 0; mt < 2; mt++)
        #pragma unroll
        for (int nt = 0; nt < 4; nt++) {
            const int row = m0 + wm * 32 + mt * 16 + g;
            const int col = n0 + wn * 32 + nt * 8 + 2 * tg;
            float2 v0 = make_float2(acc[mt][nt][0], acc[mt][nt][1]);
            float2 v1 = make_float2(acc[mt][nt][2], acc[mt][nt][3]);
            *(float2*)(C + (size_t)row * N + col)       = v0;
            *(float2*)(C + (size_t)(row + 8) * N + col) = v1;
        }
}

// ---------------------------------------------------------------------------
// Row softmax over rows of length NS (2048). One block (256 thr) per row.
// ---------------------------------------------------------------------------
__global__ void __launch_bounds__(256)
softmax_rows_kernel(float* __restrict__ P)
{
    float* p = P + (size_t)blockIdx.x * NS;
    const int t = threadIdx.x;

    float4 a = *(const float4*)(p + 4 * t);
    float4 b = *(const float4*)(p + 1024 + 4 * t);

    float m = fmaxf(fmaxf(fmaxf(a.x, a.y), fmaxf(a.z, a.w)),
                    fmaxf(fmaxf(b.x, b.y), fmaxf(b.z, b.w)));

    __shared__ float red[8];
    #pragma unroll
    for (int o = 16; o; o >>= 1)
        m = fmaxf(m, __shfl_xor_sync(0xffffffffu, m, o));
    if ((t & 31) == 0) red[t >> 5] = m;
    __syncthreads();
    m = red[0];
    #pragma unroll
    for (int w = 1; w < 8; w++) m = fmaxf(m, red[w]);
    __syncthreads();

    a.x = expf(a.x - m); a.y = expf(a.y - m);
    a.z = expf(a.z - m); a.w = expf(a.w - m);
    b.x = expf(b.x - m); b.y = expf(b.y - m);
    b.z = expf(b.z - m); b.w = expf(b.w - m);

    float s = a.x + a.y + a.z + a.w + b.x + b.y + b.z + b.w;
    #pragma unroll
    for (int o = 16; o; o >>= 1)
        s += __shfl_xor_sync(0xffffffffu, s, o);
    if ((t & 31) == 0) red[t >> 5] = s;
    __syncthreads();
    s = red[0];
    #pragma unroll
    for (int w = 1; w < 8; w++) s += red[w];

    float inv = 1.0f / s;
    a.x *= inv; a.y *= inv; a.z *= inv; a.w *= inv;
    b.x *= inv; b.y *= inv; b.z *= inv; b.w *= inv;

    *(float4*)(p + 4 * t)        = a;
    *(float4*)(p + 1024 + 4 * t) = b;
}

// ---------------------------------------------------------------------------
// Launch: e = x@We ; q,k,v = e@W* ; S = qk^T (batched) ; softmax ; y = S@v
// ---------------------------------------------------------------------------
extern "C" void kernel_launch(void* const* d_in, const int* in_sizes, int n_in,
                              void* d_out, int out_size)
{
    const float* x  = (const float*)d_in[0];
    const float* We = (const float*)d_in[1];
    const float* Wk = (const float*)d_in[2];
    const float* Wq = (const float*)d_in[3];
    const float* Wv = (const float*)d_in[4];
    float* y = (float*)d_out;

    float *e, *q, *k, *v, *s;
    cudaGetSymbolAddress((void**)&e, g_e);
    cudaGetSymbolAddress((void**)&q, g_q);
    cudaGetSymbolAddress((void**)&k, g_k);
    cudaGetSymbolAddress((void**)&v, g_v);
    cudaGetSymbolAddress((void**)&s, g_s);

    cudaFuncSetAttribute(mma_gemm<false>,
                         cudaFuncAttributeMaxDynamicSharedMemorySize, SMEM_TOTAL);
    cudaFuncSetAttribute(mma_gemm<true>,
                         cudaFuncAttributeMaxDynamicSharedMemorySize, SMEM_TOTAL);

    // 1) e = x @ W_embed           [32768,256]x[256,512]
    mma_gemm<false><<<dim3(DE / 128, MROWS / 128, 1), 512, SMEM_TOTAL>>>(
        x, We, e, MROWS, DE, DIN, 0, 0, 0);

    // 2) q,k,v = e @ W_{q,k,v}     [32768,512]x[512,512]
    mma_gemm<false><<<dim3(DE / 128, MROWS / 128, 1), 512, SMEM_TOTAL>>>(
        e, Wq, q, MROWS, DE, DE, 0, 0, 0);
    mma_gemm<false><<<dim3(DE / 128, MROWS / 128, 1), 512, SMEM_TOTAL>>>(
        e, Wk, k, MROWS, DE, DE, 0, 0, 0);
    mma_gemm<false><<<dim3(DE / 128, MROWS / 128, 1), 512, SMEM_TOTAL>>>(
        e, Wv, v, MROWS, DE, DE, 0, 0, 0);

    // 3) scores S_b = q_b @ k_b^T  [2048,512]x[2048,512]^T, batched over b
    mma_gemm<true><<<dim3(NS / 128, NS / 128, NB), 512, SMEM_TOTAL>>>(
        q, k, s, NS, NS, DE,
        (size_t)NS * DE, (size_t)NS * DE, (size_t)NS * NS);

    // 4) row softmax over keys
    softmax_rows_kernel<<<NB * NS, 256>>>(s);

    // 5) y_b = P_b @ v_b           [2048,2048]x[2048,512], batched over b
    mma_gemm<false><<<dim3(DE / 128, NS / 128, NB), 512, SMEM_TOTAL>>>(
        s, v, y, NS, DE, NS,
        (size_t)NS * NS, (size_t)NS * DE, (size_t)NS * DE);
}